// round 8
// baseline (speedup 1.0000x reference)
#include <cuda_runtime.h>
#include <cstdint>

#define N_NODES 100000
#define N_EDGES 50000
#define NNZ_TOT 500000
#define C 128

#define SCAN_B 1024
#define NB_N ((N_NODES + SCAN_B - 1) / SCAN_B)  // 98
#define NB_E ((N_EDGES + SCAN_B - 1) / SCAN_B)  // 49
#define CSR_GRID (NB_N + NB_E)                  // 147 blocks (<=148 SMs, co-resident)

#define LDA 132  // 128 + 4 padding (floats)
#define SMEM_GEMM (2 * 128 * LDA * 4)

// -------- persistent scratch (no allocations allowed) --------
__device__ float g_eagg[(size_t)N_EDGES * C];  // 25.6 MB  (B^-1 H^T X)
__device__ float g_edge[(size_t)N_EDGES * C];  // 25.6 MB  (edge_feat = eagg @ W)
__device__ int g_deg_n[N_NODES];
__device__ int g_deg_e[N_EDGES];
__device__ int g_start_n[N_NODES];
__device__ int g_start_e[N_EDGES];
__device__ int g_cur_n[N_NODES];
__device__ int g_cur_e[N_EDGES];
__device__ int g_adj_e[NNZ_TOT];   // per-edge list of node ids
__device__ int g_adj_n[NNZ_TOT];   // per-node list of edge ids
__device__ int g_bsum[CSR_GRID];
__device__ unsigned long long g_bar;  // monotone generation counter (never reset)

// software grid barrier: all CSR_GRID blocks are co-resident (1 block/SM)
__device__ __forceinline__ void grid_barrier() {
    __syncthreads();
    if (threadIdx.x == 0) {
        __threadfence();
        unsigned long long old = atomicAdd(&g_bar, 1ULL);
        unsigned long long target = (old / gridDim.x + 1ULL) * gridDim.x;
        while (*((volatile unsigned long long*)&g_bar) < target) { }
    }
    __syncthreads();
    __threadfence();
}

// -------- fused CSR build: zero -> degree -> scan -> offsets -> fill --------
__global__ __launch_bounds__(SCAN_B) void csr_build_kernel(const int* __restrict__ nidx,
                                                           const int* __restrict__ eidx) {
    __shared__ int sm[SCAN_B];
    const int tid = threadIdx.x;
    const int bid = blockIdx.x;
    const int gsz = gridDim.x * SCAN_B;
    const int gtid = bid * SCAN_B + tid;

    // phase 1: zero degree + cursor counters
    for (int i = gtid; i < N_NODES; i += gsz) { g_deg_n[i] = 0; g_cur_n[i] = 0; }
    for (int i = gtid; i < N_EDGES; i += gsz) { g_deg_e[i] = 0; g_cur_e[i] = 0; }
    grid_barrier();

    // phase 2: degree histogram
    for (int i = gtid; i < NNZ_TOT; i += gsz) {
        atomicAdd(&g_deg_n[nidx[i]], 1);
        atomicAdd(&g_deg_e[eidx[i]], 1);
    }
    grid_barrier();

    // phase 3: local block scan of this block's tile
    const int which = (bid >= NB_N);
    const int sb = which ? (bid - NB_N) : bid;       // tile index within segment
    const int n = which ? N_EDGES : N_NODES;
    const int* deg = which ? g_deg_e : g_deg_n;
    int* excl = which ? g_start_e : g_start_n;

    {
        int gid = sb * SCAN_B + tid;
        int v = (gid < n) ? deg[gid] : 0;
        sm[tid] = v;
        __syncthreads();
#pragma unroll
        for (int off = 1; off < SCAN_B; off <<= 1) {
            int t = (tid >= off) ? sm[tid - off] : 0;
            __syncthreads();
            sm[tid] += t;
            __syncthreads();
        }
        if (gid < n) excl[gid] = sm[tid] - v;  // local exclusive (no block offset yet)
        if (tid == SCAN_B - 1) g_bsum[bid] = sm[tid];
    }
    grid_barrier();

    // phase 4: add sum of predecessor block aggregates (same segment)
    {
        const int base = which ? NB_N : 0;
        int v = (tid < sb) ? g_bsum[base + tid] : 0;
        __syncthreads();  // sm reuse
        sm[tid] = v;
        __syncthreads();
#pragma unroll
        for (int off = SCAN_B / 2; off > 0; off >>= 1) {
            if (tid < off) sm[tid] += sm[tid + off];
            __syncthreads();
        }
        int boff = sm[0];
        int gid = sb * SCAN_B + tid;
        if (gid < n) excl[gid] += boff;
    }
    grid_barrier();

    // phase 5: fill CSR adjacency (counting-sort placement)
    for (int i = gtid; i < NNZ_TOT; i += gsz) {
        int nd = nidx[i];
        int e = eidx[i];
        int pe = atomicAdd(&g_cur_e[e], 1);
        g_adj_e[g_start_e[e] + pe] = nd;
        int pn = atomicAdd(&g_cur_n[nd], 1);
        g_adj_n[g_start_n[nd] + pn] = e;
    }
}

// -------- phase 1: warp per edge; eagg[e] = (1/deg_e) * sum_{v in e} x[v] --------
__global__ __launch_bounds__(256) void gather_edge_kernel(const float* __restrict__ x) {
    int g = blockIdx.x * blockDim.x + threadIdx.x;
    int e = g >> 5;
    int lane = g & 31;
    if (e >= N_EDGES) return;
    int s = g_start_e[e];
    int d = g_deg_e[e];
    float4 acc = make_float4(0.f, 0.f, 0.f, 0.f);
    int j = 0;
    for (; j + 2 <= d; j += 2) {
        int v0 = g_adj_e[s + j];
        int v1 = g_adj_e[s + j + 1];
        float4 a = __ldg((const float4*)&x[(size_t)v0 * C + lane * 4]);
        float4 b = __ldg((const float4*)&x[(size_t)v1 * C + lane * 4]);
        acc.x += a.x + b.x;
        acc.y += a.y + b.y;
        acc.z += a.z + b.z;
        acc.w += a.w + b.w;
    }
    if (j < d) {
        int v0 = g_adj_e[s + j];
        float4 a = __ldg((const float4*)&x[(size_t)v0 * C + lane * 4]);
        acc.x += a.x; acc.y += a.y; acc.z += a.z; acc.w += a.w;
    }
    float bi = (d > 0) ? (1.f / (float)d) : 0.f;
    acc.x *= bi; acc.y *= bi; acc.z *= bi; acc.w *= bi;
    *(float4*)&g_eagg[(size_t)e * C + lane * 4] = acc;
}

// -------- tf32 tensor GEMM with 3xTF32 compensation: g_edge = g_eagg @ W --------
__device__ __forceinline__ uint32_t f2tf32(float x) {
    uint32_t r;
    asm("cvt.rna.tf32.f32 %0, %1;" : "=r"(r) : "f"(x));
    return r;
}

__device__ __forceinline__ void split_tf32(float x, uint32_t& hi, uint32_t& lo) {
    hi = f2tf32(x);
    float r = x - __uint_as_float(hi);
    lo = f2tf32(r);
}

__device__ __forceinline__ void mma_tf32(float* d, const uint32_t* a, const uint32_t* b) {
    asm volatile(
        "mma.sync.aligned.m16n8k8.row.col.f32.tf32.tf32.f32 "
        "{%0,%1,%2,%3}, {%4,%5,%6,%7}, {%8,%9}, {%0,%1,%2,%3};\n"
        : "+f"(d[0]), "+f"(d[1]), "+f"(d[2]), "+f"(d[3])
        : "r"(a[0]), "r"(a[1]), "r"(a[2]), "r"(a[3]), "r"(b[0]), "r"(b[1]));
}

__global__ __launch_bounds__(256) void gemm_tf32_kernel(const float* __restrict__ W,
                                                        int M) {
    extern __shared__ float sm[];
    float* As = sm;              // [128][LDA]  row-major A tile (edge_agg)
    float* Ws = sm + 128 * LDA;  // [128][LDA]  Ws[n][k] = W[k][n]

    const int t = threadIdx.x;
    const int warp = t >> 5;
    const int lane = t & 31;
    const int g = lane >> 2;      // groupID
    const int tc = lane & 3;      // thread-in-group
    const int warpM = warp & 3;   // 0..3  (32-row stripes)
    const int warpN = warp >> 2;  // 0..1  (64-col stripes)
    const int brow = blockIdx.x * 128;

    // load A tile (128x128), zero-pad beyond M
#pragma unroll
    for (int r = 0; r < 16; r++) {
        int idx = r * 256 + t;
        int m = idx >> 5;
        int kq = idx & 31;
        int gm = brow + m;
        float4 v = make_float4(0.f, 0.f, 0.f, 0.f);
        if (gm < M) v = *(const float4*)&g_eagg[(size_t)gm * 128 + kq * 4];
        *(float4*)&As[m * LDA + kq * 4] = v;
    }
    // load W transposed: Ws[n][k] = W[k][n]
#pragma unroll
    for (int r = 0; r < 16; r++) {
        int idx = r * 256 + t;
        int k = idx >> 5;
        int nq = idx & 31;
        float4 v = *(const float4*)&W[(size_t)k * 128 + nq * 4];
        Ws[(nq * 4 + 0) * LDA + k] = v.x;
        Ws[(nq * 4 + 1) * LDA + k] = v.y;
        Ws[(nq * 4 + 2) * LDA + k] = v.z;
        Ws[(nq * 4 + 3) * LDA + k] = v.w;
    }
    __syncthreads();

    float acc[2][8][4];
#pragma unroll
    for (int i = 0; i < 2; i++)
#pragma unroll
        for (int j = 0; j < 8; j++)
#pragma unroll
            for (int q = 0; q < 4; q++) acc[i][j][q] = 0.f;

#pragma unroll 1
    for (int ks = 0; ks < 16; ks++) {
        const int k0 = ks * 8;

        uint32_t ah[2][4], al[2][4];
#pragma unroll
        for (int mf = 0; mf < 2; mf++) {
            const float* base = &As[(warpM * 32 + mf * 16) * LDA + k0];
            float a0 = base[g * LDA + tc];
            float a1 = base[(g + 8) * LDA + tc];
            float a2 = base[g * LDA + tc + 4];
            float a3 = base[(g + 8) * LDA + tc + 4];
            split_tf32(a0, ah[mf][0], al[mf][0]);
            split_tf32(a1, ah[mf][1], al[mf][1]);
            split_tf32(a2, ah[mf][2], al[mf][2]);
            split_tf32(a3, ah[mf][3], al[mf][3]);
        }

        uint32_t bh[8][2], bl[8][2];
#pragma unroll
        for (int nf = 0; nf < 8; nf++) {
            const float* base = &Ws[(warpN * 64 + nf * 8 + g) * LDA + k0];
            float b0 = base[tc];
            float b1 = base[tc + 4];
            split_tf32(b0, bh[nf][0], bl[nf][0]);
            split_tf32(b1, bh[nf][1], bl[nf][1]);
        }

#pragma unroll
        for (int mf = 0; mf < 2; mf++)
#pragma unroll
            for (int nf = 0; nf < 8; nf++) {
                mma_tf32(acc[mf][nf], ah[mf], bh[nf]);
                mma_tf32(acc[mf][nf], ah[mf], bl[nf]);
                mma_tf32(acc[mf][nf], al[mf], bh[nf]);
            }
    }

    // store accumulators to g_edge
#pragma unroll
    for (int mf = 0; mf < 2; mf++) {
        int r0 = brow + warpM * 32 + mf * 16 + g;
#pragma unroll
        for (int nf = 0; nf < 8; nf++) {
            int col = warpN * 64 + nf * 8 + tc * 2;
            if (r0 < M)
                *(float2*)&g_edge[(size_t)r0 * C + col] =
                    make_float2(acc[mf][nf][0], acc[mf][nf][1]);
            if (r0 + 8 < M)
                *(float2*)&g_edge[(size_t)(r0 + 8) * C + col] =
                    make_float2(acc[mf][nf][2], acc[mf][nf][3]);
        }
    }
}

// -------- phase 2: warp per node; out[n] = (1/deg_n) * sum_{e ni n} edge_feat[e] + b --------
__global__ __launch_bounds__(256) void gather_node_kernel(float* __restrict__ out,
                                                          const float* __restrict__ bias) {
    int g = blockIdx.x * blockDim.x + threadIdx.x;
    int nd = g >> 5;
    int lane = g & 31;
    if (nd >= N_NODES) return;
    int s = g_start_n[nd];
    int d = g_deg_n[nd];
    float4 acc = make_float4(0.f, 0.f, 0.f, 0.f);
    int j = 0;
    for (; j + 2 <= d; j += 2) {
        int e0 = g_adj_n[s + j];
        int e1 = g_adj_n[s + j + 1];
        float4 a = __ldg((const float4*)&g_edge[(size_t)e0 * C + lane * 4]);
        float4 b = __ldg((const float4*)&g_edge[(size_t)e1 * C + lane * 4]);
        acc.x += a.x + b.x;
        acc.y += a.y + b.y;
        acc.z += a.z + b.z;
        acc.w += a.w + b.w;
    }
    if (j < d) {
        int e0 = g_adj_n[s + j];
        float4 a = __ldg((const float4*)&g_edge[(size_t)e0 * C + lane * 4]);
        acc.x += a.x; acc.y += a.y; acc.z += a.z; acc.w += a.w;
    }
    float di = (d > 0) ? (1.f / (float)d) : 0.f;
    float4 bb = __ldg((const float4*)&bias[lane * 4]);
    acc.x = acc.x * di + bb.x;
    acc.y = acc.y * di + bb.y;
    acc.z = acc.z * di + bb.z;
    acc.w = acc.w * di + bb.w;
    *(float4*)&out[(size_t)nd * C + lane * 4] = acc;
}

extern "C" void kernel_launch(void* const* d_in, const int* in_sizes, int n_in,
                              void* d_out, int out_size) {
    const float* x = (const float*)d_in[0];
    const int* hei = (const int*)d_in[1];
    const float* W = (const float*)d_in[2];
    const float* b = (const float*)d_in[3];
    const int* nidx = hei;             // hyperedge_index[0]
    const int* eidx = hei + NNZ_TOT;   // hyperedge_index[1]
    float* out = (float*)d_out;

    // opt-in to 135 KB dynamic smem for the GEMM (not a stream op; capture-safe)
    cudaFuncSetAttribute(gemm_tf32_kernel, cudaFuncAttributeMaxDynamicSharedMemorySize,
                         SMEM_GEMM);

    // fused CSR build: zero -> degree -> scan -> offsets -> fill (one launch)
    csr_build_kernel<<<CSR_GRID, SCAN_B>>>(nidx, eidx);

    // node -> edge aggregation of RAW x (fused B^-1): eagg = B^-1 H^T X
    gather_edge_kernel<<<(N_EDGES * 32 + 255) / 256, 256>>>(x);

    // edge_feat = eagg @ W  (tf32 tensor cores, 3xTF32 compensation; 50k rows)
    gemm_tf32_kernel<<<(N_EDGES + 127) / 128, 256, SMEM_GEMM>>>(W, N_EDGES);

    // edge -> node (gather, fused D^-1 and bias)
    gather_node_kernel<<<(N_NODES * 32 + 255) / 256, 256>>>(out, b);
}

// round 9
// speedup vs baseline: 1.0249x; 1.0249x over previous
#include <cuda_runtime.h>
#include <cstdint>

#define N_NODES 100000
#define N_EDGES 50000
#define NNZ_TOT 500000
#define C 128

#define SCAN_B 1024
#define NB_N ((N_NODES + SCAN_B - 1) / SCAN_B)  // 98
#define NB_E ((N_EDGES + SCAN_B - 1) / SCAN_B)  // 49

#define LDA 132  // 128 + 4 padding (floats)
#define SMEM_GEMM (2 * 128 * LDA * 4)

// -------- persistent scratch (no allocations allowed) --------
__device__ float g_eagg[(size_t)N_EDGES * C];  // 25.6 MB  (B^-1 H^T X)
__device__ float g_edge[(size_t)N_EDGES * C];  // 25.6 MB  (edge_feat = eagg @ W)
__device__ int g_deg_n[N_NODES];
__device__ int g_deg_e[N_EDGES];
__device__ int g_start_n[N_NODES];   // after fill: segment END (begin = end - deg)
__device__ int g_start_e[N_EDGES];
__device__ int g_adj_e[NNZ_TOT];   // per-edge list of node ids
__device__ int g_adj_n[NNZ_TOT];   // per-node list of edge ids
__device__ int g_bsum_n[NB_N];
__device__ int g_bsum_e[NB_E];

// -------- zero degree counters --------
__global__ void zero_counts_kernel() {
    int i = blockIdx.x * blockDim.x + threadIdx.x;
    if (i < N_NODES) g_deg_n[i] = 0;
    if (i < N_EDGES) g_deg_e[i] = 0;
}

// -------- degree histogram --------
__global__ void degree_kernel(const int* __restrict__ nidx, const int* __restrict__ eidx) {
    int i = blockIdx.x * blockDim.x + threadIdx.x;
    if (i < NNZ_TOT) {
        atomicAdd(&g_deg_n[nidx[i]], 1);
        atomicAdd(&g_deg_e[eidx[i]], 1);
    }
}

// -------- two-level exclusive scan (node + edge merged per launch) --------
__global__ __launch_bounds__(SCAN_B) void scan_block_kernel() {
    int which = (blockIdx.x >= NB_N);
    int bid = which ? (blockIdx.x - NB_N) : blockIdx.x;
    int n = which ? N_EDGES : N_NODES;
    const int* deg = which ? g_deg_e : g_deg_n;
    int* excl = which ? g_start_e : g_start_n;
    int* bsum = which ? g_bsum_e : g_bsum_n;

    __shared__ int sm[SCAN_B];
    int tid = threadIdx.x;
    int gid = bid * SCAN_B + tid;
    int v = (gid < n) ? deg[gid] : 0;
    sm[tid] = v;
    __syncthreads();
#pragma unroll
    for (int off = 1; off < SCAN_B; off <<= 1) {
        int t = (tid >= off) ? sm[tid - off] : 0;
        __syncthreads();
        sm[tid] += t;
        __syncthreads();
    }
    if (gid < n) excl[gid] = sm[tid] - v;
    if (tid == SCAN_B - 1) bsum[bid] = sm[tid];
}

__global__ __launch_bounds__(128) void scan_top_kernel() {
    int which = blockIdx.x;  // 0 = node, 1 = edge
    int n = which ? NB_E : NB_N;
    int* bsum = which ? g_bsum_e : g_bsum_n;
    __shared__ int sm[128];
    int tid = threadIdx.x;
    int v = (tid < n) ? bsum[tid] : 0;
    sm[tid] = v;
    __syncthreads();
#pragma unroll
    for (int off = 1; off < 128; off <<= 1) {
        int t = (tid >= off) ? sm[tid - off] : 0;
        __syncthreads();
        sm[tid] += t;
        __syncthreads();
    }
    if (tid < n) bsum[tid] = sm[tid] - v;  // exclusive
}

__global__ __launch_bounds__(SCAN_B) void scan_add_kernel() {
    int which = (blockIdx.x >= NB_N);
    int bid = which ? (blockIdx.x - NB_N) : blockIdx.x;
    int n = which ? N_EDGES : N_NODES;
    int* excl = which ? g_start_e : g_start_n;
    const int* bsum = which ? g_bsum_e : g_bsum_n;
    int gid = bid * SCAN_B + threadIdx.x;
    if (gid < n) excl[gid] += bsum[bid];
}

// -------- fill CSR adjacency; bumps g_start_* to segment END --------
__global__ void fill_adj_kernel(const int* __restrict__ nidx, const int* __restrict__ eidx) {
    int i = blockIdx.x * blockDim.x + threadIdx.x;
    if (i >= NNZ_TOT) return;
    int n = nidx[i];
    int e = eidx[i];
    int pe = atomicAdd(&g_start_e[e], 1);
    g_adj_e[pe] = n;
    int pn = atomicAdd(&g_start_n[n], 1);
    g_adj_n[pn] = e;
}

// -------- phase 1: warp per edge; eagg[e] = (1/deg_e) * sum_{v in e} x[v] --------
__global__ __launch_bounds__(256) void gather_edge_kernel(const float* __restrict__ x) {
    int g = blockIdx.x * blockDim.x + threadIdx.x;
    int e = g >> 5;
    int lane = g & 31;
    if (e >= N_EDGES) return;
    int d = g_deg_e[e];
    int s = g_start_e[e] - d;  // begin = end - deg
    const int lofs = lane * 4;

    float4 acc = make_float4(0.f, 0.f, 0.f, 0.f);
    int j = 0;
    for (; j + 4 <= d; j += 4) {
        int v0 = __ldg(&g_adj_e[s + j]);
        int v1 = __ldg(&g_adj_e[s + j + 1]);
        int v2 = __ldg(&g_adj_e[s + j + 2]);
        int v3 = __ldg(&g_adj_e[s + j + 3]);
        float4 a = __ldg((const float4*)(x + (v0 << 7) + lofs));
        float4 b = __ldg((const float4*)(x + (v1 << 7) + lofs));
        float4 c = __ldg((const float4*)(x + (v2 << 7) + lofs));
        float4 dd = __ldg((const float4*)(x + (v3 << 7) + lofs));
        acc.x += (a.x + b.x) + (c.x + dd.x);
        acc.y += (a.y + b.y) + (c.y + dd.y);
        acc.z += (a.z + b.z) + (c.z + dd.z);
        acc.w += (a.w + b.w) + (c.w + dd.w);
    }
    if (j + 2 <= d) {
        int v0 = __ldg(&g_adj_e[s + j]);
        int v1 = __ldg(&g_adj_e[s + j + 1]);
        float4 a = __ldg((const float4*)(x + (v0 << 7) + lofs));
        float4 b = __ldg((const float4*)(x + (v1 << 7) + lofs));
        acc.x += a.x + b.x;
        acc.y += a.y + b.y;
        acc.z += a.z + b.z;
        acc.w += a.w + b.w;
        j += 2;
    }
    if (j < d) {
        int v0 = __ldg(&g_adj_e[s + j]);
        float4 a = __ldg((const float4*)(x + (v0 << 7) + lofs));
        acc.x += a.x; acc.y += a.y; acc.z += a.z; acc.w += a.w;
    }
    float bi = (d > 0) ? (1.f / (float)d) : 0.f;
    acc.x *= bi; acc.y *= bi; acc.z *= bi; acc.w *= bi;
    *(float4*)&g_eagg[(e << 7) + lofs] = acc;
}

// -------- tf32 tensor GEMM with 3xTF32 compensation: g_edge = g_eagg @ W --------
__device__ __forceinline__ uint32_t f2tf32(float x) {
    uint32_t r;
    asm("cvt.rna.tf32.f32 %0, %1;" : "=r"(r) : "f"(x));
    return r;
}

__device__ __forceinline__ void split_tf32(float x, uint32_t& hi, uint32_t& lo) {
    hi = f2tf32(x);
    float r = x - __uint_as_float(hi);
    lo = f2tf32(r);
}

__device__ __forceinline__ void mma_tf32(float* d, const uint32_t* a, const uint32_t* b) {
    asm volatile(
        "mma.sync.aligned.m16n8k8.row.col.f32.tf32.tf32.f32 "
        "{%0,%1,%2,%3}, {%4,%5,%6,%7}, {%8,%9}, {%0,%1,%2,%3};\n"
        : "+f"(d[0]), "+f"(d[1]), "+f"(d[2]), "+f"(d[3])
        : "r"(a[0]), "r"(a[1]), "r"(a[2]), "r"(a[3]), "r"(b[0]), "r"(b[1]));
}

__global__ __launch_bounds__(256) void gemm_tf32_kernel(const float* __restrict__ W,
                                                        int M) {
    extern __shared__ float sm[];
    float* As = sm;              // [128][LDA]  row-major A tile (edge_agg)
    float* Ws = sm + 128 * LDA;  // [128][LDA]  Ws[n][k] = W[k][n]

    const int t = threadIdx.x;
    const int warp = t >> 5;
    const int lane = t & 31;
    const int g = lane >> 2;      // groupID
    const int tc = lane & 3;      // thread-in-group
    const int warpM = warp & 3;   // 0..3  (32-row stripes)
    const int warpN = warp >> 2;  // 0..1  (64-col stripes)
    const int brow = blockIdx.x * 128;

    // load A tile (128x128), zero-pad beyond M
#pragma unroll
    for (int r = 0; r < 16; r++) {
        int idx = r * 256 + t;
        int m = idx >> 5;
        int kq = idx & 31;
        int gm = brow + m;
        float4 v = make_float4(0.f, 0.f, 0.f, 0.f);
        if (gm < M) v = *(const float4*)&g_eagg[(size_t)gm * 128 + kq * 4];
        *(float4*)&As[m * LDA + kq * 4] = v;
    }
    // load W transposed: Ws[n][k] = W[k][n]
#pragma unroll
    for (int r = 0; r < 16; r++) {
        int idx = r * 256 + t;
        int k = idx >> 5;
        int nq = idx & 31;
        float4 v = *(const float4*)&W[(size_t)k * 128 + nq * 4];
        Ws[(nq * 4 + 0) * LDA + k] = v.x;
        Ws[(nq * 4 + 1) * LDA + k] = v.y;
        Ws[(nq * 4 + 2) * LDA + k] = v.z;
        Ws[(nq * 4 + 3) * LDA + k] = v.w;
    }
    __syncthreads();

    float acc[2][8][4];
#pragma unroll
    for (int i = 0; i < 2; i++)
#pragma unroll
        for (int j = 0; j < 8; j++)
#pragma unroll
            for (int q = 0; q < 4; q++) acc[i][j][q] = 0.f;

#pragma unroll 1
    for (int ks = 0; ks < 16; ks++) {
        const int k0 = ks * 8;

        uint32_t ah[2][4], al[2][4];
#pragma unroll
        for (int mf = 0; mf < 2; mf++) {
            const float* base = &As[(warpM * 32 + mf * 16) * LDA + k0];
            float a0 = base[g * LDA + tc];
            float a1 = base[(g + 8) * LDA + tc];
            float a2 = base[g * LDA + tc + 4];
            float a3 = base[(g + 8) * LDA + tc + 4];
            split_tf32(a0, ah[mf][0], al[mf][0]);
            split_tf32(a1, ah[mf][1], al[mf][1]);
            split_tf32(a2, ah[mf][2], al[mf][2]);
            split_tf32(a3, ah[mf][3], al[mf][3]);
        }

        uint32_t bh[8][2], bl[8][2];
#pragma unroll
        for (int nf = 0; nf < 8; nf++) {
            const float* base = &Ws[(warpN * 64 + nf * 8 + g) * LDA + k0];
            float b0 = base[tc];
            float b1 = base[tc + 4];
            split_tf32(b0, bh[nf][0], bl[nf][0]);
            split_tf32(b1, bh[nf][1], bl[nf][1]);
        }

#pragma unroll
        for (int mf = 0; mf < 2; mf++)
#pragma unroll
            for (int nf = 0; nf < 8; nf++) {
                mma_tf32(acc[mf][nf], ah[mf], bh[nf]);
                mma_tf32(acc[mf][nf], ah[mf], bl[nf]);
                mma_tf32(acc[mf][nf], al[mf], bh[nf]);
            }
    }

    // store accumulators to g_edge
#pragma unroll
    for (int mf = 0; mf < 2; mf++) {
        int r0 = brow + warpM * 32 + mf * 16 + g;
#pragma unroll
        for (int nf = 0; nf < 8; nf++) {
            int col = warpN * 64 + nf * 8 + tc * 2;
            if (r0 < M)
                *(float2*)&g_edge[(size_t)r0 * C + col] =
                    make_float2(acc[mf][nf][0], acc[mf][nf][1]);
            if (r0 + 8 < M)
                *(float2*)&g_edge[(size_t)(r0 + 8) * C + col] =
                    make_float2(acc[mf][nf][2], acc[mf][nf][3]);
        }
    }
}

// -------- phase 2: warp per node; out[n] = (1/deg_n) * sum_{e ni n} edge_feat[e] + b --------
__global__ __launch_bounds__(256) void gather_node_kernel(float* __restrict__ out,
                                                          const float* __restrict__ bias) {
    int g = blockIdx.x * blockDim.x + threadIdx.x;
    int nd = g >> 5;
    int lane = g & 31;
    if (nd >= N_NODES) return;
    int d = g_deg_n[nd];
    int s = g_start_n[nd] - d;  // begin = end - deg
    const int lofs = lane * 4;
    const float* ef = g_edge;

    float4 acc = make_float4(0.f, 0.f, 0.f, 0.f);
    int j = 0;
    for (; j + 4 <= d; j += 4) {
        int e0 = __ldg(&g_adj_n[s + j]);
        int e1 = __ldg(&g_adj_n[s + j + 1]);
        int e2 = __ldg(&g_adj_n[s + j + 2]);
        int e3 = __ldg(&g_adj_n[s + j + 3]);
        float4 a = __ldg((const float4*)(ef + (e0 << 7) + lofs));
        float4 b = __ldg((const float4*)(ef + (e1 << 7) + lofs));
        float4 c = __ldg((const float4*)(ef + (e2 << 7) + lofs));
        float4 dd = __ldg((const float4*)(ef + (e3 << 7) + lofs));
        acc.x += (a.x + b.x) + (c.x + dd.x);
        acc.y += (a.y + b.y) + (c.y + dd.y);
        acc.z += (a.z + b.z) + (c.z + dd.z);
        acc.w += (a.w + b.w) + (c.w + dd.w);
    }
    if (j + 2 <= d) {
        int e0 = __ldg(&g_adj_n[s + j]);
        int e1 = __ldg(&g_adj_n[s + j + 1]);
        float4 a = __ldg((const float4*)(ef + (e0 << 7) + lofs));
        float4 b = __ldg((const float4*)(ef + (e1 << 7) + lofs));
        acc.x += a.x + b.x;
        acc.y += a.y + b.y;
        acc.z += a.z + b.z;
        acc.w += a.w + b.w;
        j += 2;
    }
    if (j < d) {
        int e0 = __ldg(&g_adj_n[s + j]);
        float4 a = __ldg((const float4*)(ef + (e0 << 7) + lofs));
        acc.x += a.x; acc.y += a.y; acc.z += a.z; acc.w += a.w;
    }
    float di = (d > 0) ? (1.f / (float)d) : 0.f;
    float4 bb = __ldg((const float4*)&bias[lofs]);
    acc.x = acc.x * di + bb.x;
    acc.y = acc.y * di + bb.y;
    acc.z = acc.z * di + bb.z;
    acc.w = acc.w * di + bb.w;
    *(float4*)&out[((size_t)nd << 7) + lofs] = acc;
}

extern "C" void kernel_launch(void* const* d_in, const int* in_sizes, int n_in,
                              void* d_out, int out_size) {
    const float* x = (const float*)d_in[0];
    const int* hei = (const int*)d_in[1];
    const float* W = (const float*)d_in[2];
    const float* b = (const float*)d_in[3];
    const int* nidx = hei;             // hyperedge_index[0]
    const int* eidx = hei + NNZ_TOT;   // hyperedge_index[1]
    float* out = (float*)d_out;

    // opt-in to 135 KB dynamic smem for the GEMM (not a stream op; capture-safe)
    cudaFuncSetAttribute(gemm_tf32_kernel, cudaFuncAttributeMaxDynamicSharedMemorySize,
                         SMEM_GEMM);

    // CSR build
    zero_counts_kernel<<<(N_NODES + 255) / 256, 256>>>();
    degree_kernel<<<(NNZ_TOT + 255) / 256, 256>>>(nidx, eidx);

    scan_block_kernel<<<NB_N + NB_E, SCAN_B>>>();
    scan_top_kernel<<<2, 128>>>();
    scan_add_kernel<<<NB_N + NB_E, SCAN_B>>>();

    fill_adj_kernel<<<(NNZ_TOT + 255) / 256, 256>>>(nidx, eidx);

    // node -> edge aggregation of RAW x (fused B^-1): eagg = B^-1 H^T X
    gather_edge_kernel<<<(N_EDGES * 32 + 255) / 256, 256>>>(x);

    // edge_feat = eagg @ W  (tf32 tensor cores, 3xTF32 compensation; 50k rows)
    gemm_tf32_kernel<<<(N_EDGES + 127) / 128, 256, SMEM_GEMM>>>(W, N_EDGES);

    // edge -> node (gather, fused D^-1 and bias)
    gather_node_kernel<<<(N_NODES * 32 + 255) / 256, 256>>>(out, b);
}

// round 10
// speedup vs baseline: 1.1778x; 1.1492x over previous
#include <cuda_runtime.h>
#include <cstdint>

#define N_NODES 100000
#define N_EDGES 50000
#define NNZ_TOT 500000
#define C 128

#define SCAN_B 1024
#define NB_N ((N_NODES + SCAN_B - 1) / SCAN_B)  // 98
#define NB_E ((N_EDGES + SCAN_B - 1) / SCAN_B)  // 49

#define LDP 68  // pair-stride (uint32) for bf16x2 planes: bank = 4g+tc, conflict-free
#define SMEM_GEMM (4 * 128 * LDP * 4)  // Ah, Al, Bh, Bl = 139264 B

// -------- persistent scratch (no allocations allowed) --------
__device__ float g_eagg[(size_t)N_EDGES * C];  // 25.6 MB  (B^-1 H^T X)
__device__ float g_edge[(size_t)N_EDGES * C];  // 25.6 MB  (edge_feat = eagg @ W)
__device__ int g_deg_n[N_NODES];
__device__ int g_deg_e[N_EDGES];
__device__ int g_start_n[N_NODES];   // after fill: segment END (begin = end - deg)
__device__ int g_start_e[N_EDGES];
__device__ int g_adj_e[NNZ_TOT];   // per-edge list of node ids
__device__ int g_adj_n[NNZ_TOT];   // per-node list of edge ids
__device__ int g_bsum_n[NB_N];
__device__ int g_bsum_e[NB_E];

// -------- zero degree counters --------
__global__ void zero_counts_kernel() {
    int i = blockIdx.x * blockDim.x + threadIdx.x;
    if (i < N_NODES) g_deg_n[i] = 0;
    if (i < N_EDGES) g_deg_e[i] = 0;
}

// -------- degree histogram --------
__global__ void degree_kernel(const int* __restrict__ nidx, const int* __restrict__ eidx) {
    int i = blockIdx.x * blockDim.x + threadIdx.x;
    if (i < NNZ_TOT) {
        atomicAdd(&g_deg_n[nidx[i]], 1);
        atomicAdd(&g_deg_e[eidx[i]], 1);
    }
}

// -------- block-local exclusive scan (node + edge merged per launch) --------
__global__ __launch_bounds__(SCAN_B) void scan_block_kernel() {
    int which = (blockIdx.x >= NB_N);
    int bid = which ? (blockIdx.x - NB_N) : blockIdx.x;
    int n = which ? N_EDGES : N_NODES;
    const int* deg = which ? g_deg_e : g_deg_n;
    int* excl = which ? g_start_e : g_start_n;
    int* bsum = which ? g_bsum_e : g_bsum_n;

    __shared__ int sm[SCAN_B];
    int tid = threadIdx.x;
    int gid = bid * SCAN_B + tid;
    int v = (gid < n) ? deg[gid] : 0;
    sm[tid] = v;
    __syncthreads();
#pragma unroll
    for (int off = 1; off < SCAN_B; off <<= 1) {
        int t = (tid >= off) ? sm[tid - off] : 0;
        __syncthreads();
        sm[tid] += t;
        __syncthreads();
    }
    if (gid < n) excl[gid] = sm[tid] - v;
    if (tid == SCAN_B - 1) bsum[bid] = sm[tid];
}

// -------- add predecessor block sums (scan_top folded in as reduction) --------
__global__ __launch_bounds__(SCAN_B) void scan_add_kernel() {
    int which = (blockIdx.x >= NB_N);
    int sb = which ? (blockIdx.x - NB_N) : blockIdx.x;
    int n = which ? N_EDGES : N_NODES;
    int* excl = which ? g_start_e : g_start_n;
    const int* bsum = which ? g_bsum_e : g_bsum_n;

    __shared__ int sm[128];
    int tid = threadIdx.x;
    if (tid < 128) sm[tid] = (tid < sb) ? bsum[tid] : 0;
    __syncthreads();
#pragma unroll
    for (int off = 64; off > 0; off >>= 1) {
        if (tid < off) sm[tid] += sm[tid + off];
        __syncthreads();
    }
    int boff = sm[0];
    int gid = sb * SCAN_B + tid;
    if (gid < n) excl[gid] += boff;
}

// -------- fill CSR adjacency; bumps g_start_* to segment END --------
__global__ void fill_adj_kernel(const int* __restrict__ nidx, const int* __restrict__ eidx) {
    int i = blockIdx.x * blockDim.x + threadIdx.x;
    if (i >= NNZ_TOT) return;
    int n = nidx[i];
    int e = eidx[i];
    int pe = atomicAdd(&g_start_e[e], 1);
    g_adj_e[pe] = n;
    int pn = atomicAdd(&g_start_n[n], 1);
    g_adj_n[pn] = e;
}

// -------- phase 1: warp per edge; eagg[e] = (1/deg_e) * sum_{v in e} x[v] --------
__global__ __launch_bounds__(256) void gather_edge_kernel(const float* __restrict__ x) {
    int g = blockIdx.x * blockDim.x + threadIdx.x;
    int e = g >> 5;
    int lane = g & 31;
    if (e >= N_EDGES) return;
    int d = g_deg_e[e];
    int s = g_start_e[e] - d;  // begin = end - deg
    const int lofs = lane * 4;

    float4 acc = make_float4(0.f, 0.f, 0.f, 0.f);
    int j = 0;
    for (; j + 4 <= d; j += 4) {
        int v0 = __ldg(&g_adj_e[s + j]);
        int v1 = __ldg(&g_adj_e[s + j + 1]);
        int v2 = __ldg(&g_adj_e[s + j + 2]);
        int v3 = __ldg(&g_adj_e[s + j + 3]);
        float4 a = __ldg((const float4*)(x + (v0 << 7) + lofs));
        float4 b = __ldg((const float4*)(x + (v1 << 7) + lofs));
        float4 c = __ldg((const float4*)(x + (v2 << 7) + lofs));
        float4 dd = __ldg((const float4*)(x + (v3 << 7) + lofs));
        acc.x += (a.x + b.x) + (c.x + dd.x);
        acc.y += (a.y + b.y) + (c.y + dd.y);
        acc.z += (a.z + b.z) + (c.z + dd.z);
        acc.w += (a.w + b.w) + (c.w + dd.w);
    }
    if (j + 2 <= d) {
        int v0 = __ldg(&g_adj_e[s + j]);
        int v1 = __ldg(&g_adj_e[s + j + 1]);
        float4 a = __ldg((const float4*)(x + (v0 << 7) + lofs));
        float4 b = __ldg((const float4*)(x + (v1 << 7) + lofs));
        acc.x += a.x + b.x;
        acc.y += a.y + b.y;
        acc.z += a.z + b.z;
        acc.w += a.w + b.w;
        j += 2;
    }
    if (j < d) {
        int v0 = __ldg(&g_adj_e[s + j]);
        float4 a = __ldg((const float4*)(x + (v0 << 7) + lofs));
        acc.x += a.x; acc.y += a.y; acc.z += a.z; acc.w += a.w;
    }
    float bi = (d > 0) ? (1.f / (float)d) : 0.f;
    acc.x *= bi; acc.y *= bi; acc.z *= bi; acc.w *= bi;
    *(float4*)&g_eagg[(e << 7) + lofs] = acc;
}

// -------- bf16 split helpers --------
// pack (x0, x1) as bf16x2 (lo = x0, hi = x1) and produce hi + lo planes
__device__ __forceinline__ void cvt_pair(float x0, float x1, uint32_t& hi, uint32_t& lo) {
    asm("cvt.rn.bf16x2.f32 %0, %1, %2;" : "=r"(hi) : "f"(x1), "f"(x0));
    float h0 = __uint_as_float(hi << 16);
    float h1 = __uint_as_float(hi & 0xffff0000u);
    asm("cvt.rn.bf16x2.f32 %0, %1, %2;" : "=r"(lo) : "f"(x1 - h1), "f"(x0 - h0));
}

__device__ __forceinline__ void mma_bf16(float* d, const uint32_t* a, const uint32_t* b) {
    asm volatile(
        "mma.sync.aligned.m16n8k16.row.col.f32.bf16.bf16.f32 "
        "{%0,%1,%2,%3}, {%4,%5,%6,%7}, {%8,%9}, {%0,%1,%2,%3};\n"
        : "+f"(d[0]), "+f"(d[1]), "+f"(d[2]), "+f"(d[3])
        : "r"(a[0]), "r"(a[1]), "r"(a[2]), "r"(a[3]), "r"(b[0]), "r"(b[1]));
}

// -------- bf16x3 tensor GEMM: g_edge = g_eagg @ W  (hi/lo planes pre-split in smem) --------
__global__ __launch_bounds__(256) void gemm_bf16_kernel(const float* __restrict__ W,
                                                        int M) {
    extern __shared__ uint32_t smu[];
    uint32_t* Ah = smu;                  // [128][LDP] bf16x2 pairs (k-pairs)
    uint32_t* Al = Ah + 128 * LDP;
    uint32_t* Bh = Al + 128 * LDP;       // Bh[n][kp] = (W[2kp][n], W[2kp+1][n])
    uint32_t* Bl = Bh + 128 * LDP;

    const int t = threadIdx.x;
    const int warp = t >> 5;
    const int lane = t & 31;
    const int g = lane >> 2;      // groupID 0..7
    const int tc = lane & 3;      // thread-in-group 0..3
    const int warpM = warp & 3;   // 0..3  (32-row stripes)
    const int warpN = warp >> 2;  // 0..1  (64-col stripes)
    const int brow = blockIdx.x * 128;

    // load + split A tile (128 rows x 32 float4 = 64 pairs per row)
#pragma unroll
    for (int r = 0; r < 16; r++) {
        int idx = r * 256 + t;
        int m = idx >> 5;
        int q = idx & 31;  // float4 index -> pairs 2q, 2q+1
        int gm = brow + m;
        float4 v = make_float4(0.f, 0.f, 0.f, 0.f);
        if (gm < M) v = *(const float4*)&g_eagg[(size_t)gm * 128 + q * 4];
        uint32_t h0, l0, h1, l1;
        cvt_pair(v.x, v.y, h0, l0);
        cvt_pair(v.z, v.w, h1, l1);
        Ah[m * LDP + 2 * q] = h0;
        Ah[m * LDP + 2 * q + 1] = h1;
        Al[m * LDP + 2 * q] = l0;
        Al[m * LDP + 2 * q + 1] = l1;
    }
    // load + split W transposed into k-pairs: Bh[n][kp] = (W[2kp][n], W[2kp+1][n])
#pragma unroll
    for (int r = 0; r < 8; r++) {
        int idx = r * 256 + t;   // 2048 total = 64 kp x 32 nq
        int kp = idx >> 5;       // pair index 0..63
        int nq = idx & 31;       // float4 col group
        int k = kp * 2;
        float4 v0 = *(const float4*)&W[(size_t)k * 128 + nq * 4];
        float4 v1 = *(const float4*)&W[(size_t)(k + 1) * 128 + nq * 4];
        const float* p0 = &v0.x;
        const float* p1 = &v1.x;
#pragma unroll
        for (int j = 0; j < 4; j++) {
            int n = nq * 4 + j;
            uint32_t h, l;
            cvt_pair(p0[j], p1[j], h, l);
            Bh[n * LDP + kp] = h;
            Bl[n * LDP + kp] = l;
        }
    }
    __syncthreads();

    float acc[2][8][4];
#pragma unroll
    for (int i = 0; i < 2; i++)
#pragma unroll
        for (int j = 0; j < 8; j++)
#pragma unroll
            for (int q = 0; q < 4; q++) acc[i][j][q] = 0.f;

#pragma unroll 1
    for (int ks = 0; ks < 8; ks++) {
        const int p0 = ks * 8;  // 8 k-pairs = K=16 per step

        uint32_t a_h[2][4], a_l[2][4];
#pragma unroll
        for (int mf = 0; mf < 2; mf++) {
            int r0 = (warpM * 32 + mf * 16 + g) * LDP;
            int r1 = r0 + 8 * LDP;
            a_h[mf][0] = Ah[r0 + p0 + tc];
            a_h[mf][1] = Ah[r1 + p0 + tc];
            a_h[mf][2] = Ah[r0 + p0 + 4 + tc];
            a_h[mf][3] = Ah[r1 + p0 + 4 + tc];
            a_l[mf][0] = Al[r0 + p0 + tc];
            a_l[mf][1] = Al[r1 + p0 + tc];
            a_l[mf][2] = Al[r0 + p0 + 4 + tc];
            a_l[mf][3] = Al[r1 + p0 + 4 + tc];
        }

        uint32_t b_h[8][2], b_l[8][2];
#pragma unroll
        for (int nf = 0; nf < 8; nf++) {
            int nb = (warpN * 64 + nf * 8 + g) * LDP;
            b_h[nf][0] = Bh[nb + p0 + tc];
            b_h[nf][1] = Bh[nb + p0 + 4 + tc];
            b_l[nf][0] = Bl[nb + p0 + tc];
            b_l[nf][1] = Bl[nb + p0 + 4 + tc];
        }

#pragma unroll
        for (int mf = 0; mf < 2; mf++)
#pragma unroll
            for (int nf = 0; nf < 8; nf++) {
                mma_bf16(acc[mf][nf], a_h[mf], b_h[nf]);
                mma_bf16(acc[mf][nf], a_h[mf], b_l[nf]);
                mma_bf16(acc[mf][nf], a_l[mf], b_h[nf]);
            }
    }

    // store accumulators to g_edge
#pragma unroll
    for (int mf = 0; mf < 2; mf++) {
        int r0 = brow + warpM * 32 + mf * 16 + g;
#pragma unroll
        for (int nf = 0; nf < 8; nf++) {
            int col = warpN * 64 + nf * 8 + tc * 2;
            if (r0 < M)
                *(float2*)&g_edge[(size_t)r0 * C + col] =
                    make_float2(acc[mf][nf][0], acc[mf][nf][1]);
            if (r0 + 8 < M)
                *(float2*)&g_edge[(size_t)(r0 + 8) * C + col] =
                    make_float2(acc[mf][nf][2], acc[mf][nf][3]);
        }
    }
}

// -------- phase 2: warp per node; out[n] = (1/deg_n) * sum_{e ni n} edge_feat[e] + b --------
__global__ __launch_bounds__(256) void gather_node_kernel(float* __restrict__ out,
                                                          const float* __restrict__ bias) {
    int g = blockIdx.x * blockDim.x + threadIdx.x;
    int nd = g >> 5;
    int lane = g & 31;
    if (nd >= N_NODES) return;
    int d = g_deg_n[nd];
    int s = g_start_n[nd] - d;  // begin = end - deg
    const int lofs = lane * 4;
    const float* ef = g_edge;

    float4 acc = make_float4(0.f, 0.f, 0.f, 0.f);
    int j = 0;
    for (; j + 4 <= d; j += 4) {
        int e0 = __ldg(&g_adj_n[s + j]);
        int e1 = __ldg(&g_adj_n[s + j + 1]);
        int e2 = __ldg(&g_adj_n[s + j + 2]);
        int e3 = __ldg(&g_adj_n[s + j + 3]);
        float4 a = __ldg((const float4*)(ef + (e0 << 7) + lofs));
        float4 b = __ldg((const float4*)(ef + (e1 << 7) + lofs));
        float4 c = __ldg((const float4*)(ef + (e2 << 7) + lofs));
        float4 dd = __ldg((const float4*)(ef + (e3 << 7) + lofs));
        acc.x += (a.x + b.x) + (c.x + dd.x);
        acc.y += (a.y + b.y) + (c.y + dd.y);
        acc.z += (a.z + b.z) + (c.z + dd.z);
        acc.w += (a.w + b.w) + (c.w + dd.w);
    }
    if (j + 2 <= d) {
        int e0 = __ldg(&g_adj_n[s + j]);
        int e1 = __ldg(&g_adj_n[s + j + 1]);
        float4 a = __ldg((const float4*)(ef + (e0 << 7) + lofs));
        float4 b = __ldg((const float4*)(ef + (e1 << 7) + lofs));
        acc.x += a.x + b.x;
        acc.y += a.y + b.y;
        acc.z += a.z + b.z;
        acc.w += a.w + b.w;
        j += 2;
    }
    if (j < d) {
        int e0 = __ldg(&g_adj_n[s + j]);
        float4 a = __ldg((const float4*)(ef + (e0 << 7) + lofs));
        acc.x += a.x; acc.y += a.y; acc.z += a.z; acc.w += a.w;
    }
    float di = (d > 0) ? (1.f / (float)d) : 0.f;
    float4 bb = __ldg((const float4*)&bias[lofs]);
    acc.x = acc.x * di + bb.x;
    acc.y = acc.y * di + bb.y;
    acc.z = acc.z * di + bb.z;
    acc.w = acc.w * di + bb.w;
    *(float4*)&out[((size_t)nd << 7) + lofs] = acc;
}

extern "C" void kernel_launch(void* const* d_in, const int* in_sizes, int n_in,
                              void* d_out, int out_size) {
    const float* x = (const float*)d_in[0];
    const int* hei = (const int*)d_in[1];
    const float* W = (const float*)d_in[2];
    const float* b = (const float*)d_in[3];
    const int* nidx = hei;             // hyperedge_index[0]
    const int* eidx = hei + NNZ_TOT;   // hyperedge_index[1]
    float* out = (float*)d_out;

    // opt-in to 136 KB dynamic smem for the GEMM (attribute set, not a stream op)
    cudaFuncSetAttribute(gemm_bf16_kernel, cudaFuncAttributeMaxDynamicSharedMemorySize,
                         SMEM_GEMM);

    // CSR build
    zero_counts_kernel<<<(N_NODES + 255) / 256, 256>>>();
    degree_kernel<<<(NNZ_TOT + 255) / 256, 256>>>(nidx, eidx);

    scan_block_kernel<<<NB_N + NB_E, SCAN_B>>>();
    scan_add_kernel<<<NB_N + NB_E, SCAN_B>>>();

    fill_adj_kernel<<<(NNZ_TOT + 255) / 256, 256>>>(nidx, eidx);

    // node -> edge aggregation of RAW x (fused B^-1): eagg = B^-1 H^T X
    gather_edge_kernel<<<(N_EDGES * 32 + 255) / 256, 256>>>(x);

    // edge_feat = eagg @ W  (bf16x3 hi/lo tensor cores; 50k rows)
    gemm_bf16_kernel<<<(N_EDGES + 127) / 128, 256, SMEM_GEMM>>>(W, N_EDGES);

    // edge -> node (gather, fused D^-1 and bias)
    gather_node_kernel<<<(N_NODES * 32 + 255) / 256, 256>>>(out, b);
}